// round 5
// baseline (speedup 1.0000x reference)
#include <cuda_runtime.h>

#define NN 200000
#define EE 3200000
#define HH 16
#define CC 4
#define GG 256

// Scratch (allocation-free: __device__ globals). 16B alignment for float4/RED.128.
__device__ __align__(16) float g_deg[NN];        // degree, then dinv (in-place)
__device__ int   g_src[EE];
__device__ int   g_dst[EE];
__device__ __align__(16) float g_norm[EE];
__device__ __align__(16) float g_t[NN * HH];     // transformed features (gather source)
__device__ __align__(16) float g_acc[NN * HH];   // scatter accumulator / layer output

__global__ void zero_deg_kernel() {
    int n = blockIdx.x * blockDim.x + threadIdx.x;
    if (n < NN) g_deg[n] = 0.0f;
}

// edge_index arrives as int32 (harness converts int64 -> int32).
// Copy src/dst rows + accumulate in-degree at dst.
__global__ void deg_kernel(const int* __restrict__ ei) {
    int e = blockIdx.x * blockDim.x + threadIdx.x;
    if (e >= EE) return;
    int s = ei[e];
    int d = ei[EE + e];
    g_src[e] = s;
    g_dst[e] = d;
    atomicAdd(&g_deg[d], 1.0f);
}

// deg -> dinv = rsqrt(deg + 1)   (+1 = self-loop)
__global__ void dinv_kernel() {
    int n = blockIdx.x * blockDim.x + threadIdx.x;
    if (n < NN) g_deg[n] = rsqrtf(g_deg[n] + 1.0f);
}

// per-edge symmetric norm, computed once, reused by all 3 layers
__global__ void norm_kernel() {
    int e = blockIdx.x * blockDim.x + threadIdx.x;
    if (e < EE) g_norm[e] = g_deg[g_src[e]] * g_deg[g_dst[e]];
}

// Fused: (optional bias+ReLU of previous layer) -> h @ W -> write g_t,
// and initialize g_acc with the self-loop contribution t * dinv^2.
template <bool FIRST>
__global__ void transform_kernel(const float* __restrict__ in,
                                 const float* __restrict__ W,
                                 const float* __restrict__ bprev) {
    __shared__ float Ws[HH * HH];
    __shared__ float Bs[HH];
    int tid = threadIdx.x;
    if (tid < HH * HH) Ws[tid] = W[tid];
    if (!FIRST && tid < HH) Bs[tid] = bprev[tid];
    __syncthreads();

    int n = blockIdx.x * blockDim.x + tid;
    if (n >= NN) return;

    float h[HH];
    if (FIRST) {
        const float4* p = (const float4*)(in + (size_t)n * HH);
#pragma unroll
        for (int q = 0; q < 4; q++) {
            float4 v = p[q];
            h[q * 4 + 0] = v.x; h[q * 4 + 1] = v.y;
            h[q * 4 + 2] = v.z; h[q * 4 + 3] = v.w;
        }
    } else {
        const float4* p = (const float4*)(g_acc + (size_t)n * HH);
#pragma unroll
        for (int q = 0; q < 4; q++) {
            float4 v = p[q];
            h[q * 4 + 0] = fmaxf(v.x + Bs[q * 4 + 0], 0.0f);
            h[q * 4 + 1] = fmaxf(v.y + Bs[q * 4 + 1], 0.0f);
            h[q * 4 + 2] = fmaxf(v.z + Bs[q * 4 + 2], 0.0f);
            h[q * 4 + 3] = fmaxf(v.w + Bs[q * 4 + 3], 0.0f);
        }
    }

    float o[HH];
#pragma unroll
    for (int j = 0; j < HH; j++) o[j] = 0.0f;
#pragma unroll
    for (int k = 0; k < HH; k++) {
#pragma unroll
        for (int j = 0; j < HH; j += 4) {
            float4 w = *(const float4*)&Ws[k * HH + j];
            o[j + 0] += h[k] * w.x;
            o[j + 1] += h[k] * w.y;
            o[j + 2] += h[k] * w.z;
            o[j + 3] += h[k] * w.w;
        }
    }

    float di = g_deg[n];      // holds dinv at this point
    float d2 = di * di;       // self-loop norm
    float4* tp = (float4*)(g_t + (size_t)n * HH);
    float4* ap = (float4*)(g_acc + (size_t)n * HH);
#pragma unroll
    for (int q = 0; q < 4; q++) {
        float4 v = make_float4(o[q * 4 + 0], o[q * 4 + 1], o[q * 4 + 2], o[q * 4 + 3]);
        tp[q] = v;
        ap[q] = make_float4(v.x * d2, v.y * d2, v.z * d2, v.w * d2);
    }
}

// Edge scatter: acc[dst] += t[src] * norm. 4 threads per edge,
// each thread: one 16B gather + one 16B vector reduction (red.global.add.v4.f32).
__global__ void scatter_kernel() {
    int gid = blockIdx.x * blockDim.x + threadIdx.x;
    if (gid >= EE * 4) return;
    int e = gid >> 2;
    int c = gid & 3;
    int s = g_src[e];
    int d = g_dst[e];
    float w = g_norm[e];
    float4 v = __ldg((const float4*)(g_t + (size_t)s * HH) + c);
    v.x *= w; v.y *= w; v.z *= w; v.w *= w;
    float* a = g_acc + (size_t)d * HH + c * 4;
    asm volatile("red.global.add.v4.f32 [%0], {%1, %2, %3, %4};"
                 :: "l"(a), "f"(v.x), "f"(v.y), "f"(v.z), "f"(v.w)
                 : "memory");
}

// One block per graph: binary-search the sorted batch array for the node
// range, atomic-free block reduction, then head (16->4) + log_softmax.
__global__ void pool_head_kernel(const int* __restrict__ batch,
                                 const float* __restrict__ b3,
                                 const float* __restrict__ Wlin,
                                 const float* __restrict__ blin,
                                 float* __restrict__ out) {
    int g = blockIdx.x;
    int tid = threadIdx.x;

    // lower_bound(batch, g) and lower_bound(batch, g+1)
    int lo = 0, hi = NN;
    while (lo < hi) { int m = (lo + hi) >> 1; if (batch[m] < g) lo = m + 1; else hi = m; }
    int beg = lo;
    lo = beg; hi = NN;
    int g1 = g + 1;
    while (lo < hi) { int m = (lo + hi) >> 1; if (batch[m] < g1) lo = m + 1; else hi = m; }
    int end = lo;

    float s[HH];
#pragma unroll
    for (int f = 0; f < HH; f++) s[f] = 0.0f;

    for (int n = beg + tid; n < end; n += blockDim.x) {
        const float4* p = (const float4*)(g_acc + (size_t)n * HH);
#pragma unroll
        for (int q = 0; q < 4; q++) {
            float4 v = p[q];
            s[q * 4 + 0] += v.x; s[q * 4 + 1] += v.y;
            s[q * 4 + 2] += v.z; s[q * 4 + 3] += v.w;
        }
    }

    // warp reduce
#pragma unroll
    for (int off = 16; off > 0; off >>= 1) {
#pragma unroll
        for (int f = 0; f < HH; f++)
            s[f] += __shfl_down_sync(0xffffffffu, s[f], off);
    }

    __shared__ float red[8][HH];
    int warp = tid >> 5, lane = tid & 31;
    if (lane == 0) {
#pragma unroll
        for (int f = 0; f < HH; f++) red[warp][f] = s[f];
    }
    __syncthreads();

    if (tid == 0) {
        float tot[HH];
        int nwarps = blockDim.x >> 5;
#pragma unroll
        for (int f = 0; f < HH; f++) {
            float t = 0.0f;
            for (int w = 0; w < nwarps; w++) t += red[w][f];
            tot[f] = t;
        }
        float cnt = (float)(end - beg);
        float inv = 1.0f / fmaxf(cnt, 1.0f);
        float pooled[HH];
#pragma unroll
        for (int f = 0; f < HH; f++) pooled[f] = (tot[f] + cnt * b3[f]) * inv;

        float logit[CC];
#pragma unroll
        for (int c = 0; c < CC; c++) {
            float a = blin[c];
#pragma unroll
            for (int f = 0; f < HH; f++) a += pooled[f] * Wlin[f * CC + c];
            logit[c] = a;
        }
        float m = logit[0];
#pragma unroll
        for (int c = 1; c < CC; c++) m = fmaxf(m, logit[c]);
        float se = 0.0f;
#pragma unroll
        for (int c = 0; c < CC; c++) se += expf(logit[c] - m);
        float lse = m + logf(se);
#pragma unroll
        for (int c = 0; c < CC; c++) out[g * CC + c] = logit[c] - lse;
    }
}

extern "C" void kernel_launch(void* const* d_in, const int* in_sizes, int n_in,
                              void* d_out, int out_size) {
    // Identify inputs by element count (robust to metadata.txt ordering).
    // Unique sizes: x=3.2M, edge_index=6.4M (int32), batch=200K (int32),
    // Wlin=64, blin=4. Same-size series (W=256 x3, b=16 x3) keep appearance order.
    const float *x = 0, *W1 = 0, *b1 = 0, *W2 = 0, *b2 = 0, *W3 = 0, *b3 = 0;
    const float *Wlin = 0, *blin = 0;
    const int *ei = 0, *batch = 0;
    int wseen = 0, bseen = 0;
    for (int i = 0; i < n_in; i++) {
        int s = in_sizes[i];
        const void* p = d_in[i];
        if (s == NN * HH)        x = (const float*)p;     // 3,200,000
        else if (s == 2 * EE)    ei = (const int*)p;      // 6,400,000
        else if (s == NN)        batch = (const int*)p;   // 200,000
        else if (s == HH * HH) { // 256
            if (wseen == 0) W1 = (const float*)p;
            else if (wseen == 1) W2 = (const float*)p;
            else W3 = (const float*)p;
            wseen++;
        } else if (s == HH) {    // 16
            if (bseen == 0) b1 = (const float*)p;
            else if (bseen == 1) b2 = (const float*)p;
            else b3 = (const float*)p;
            bseen++;
        } else if (s == HH * CC) Wlin = (const float*)p;  // 64
        else if (s == CC)        blin = (const float*)p;  // 4
    }
    float* out = (float*)d_out;

    const int B = 256;
    const int gN = (NN + B - 1) / B;
    const int gE = (EE + B - 1) / B;
    const int gE4 = (EE * 4 + B - 1) / B;

    zero_deg_kernel<<<gN, B>>>();
    deg_kernel<<<gE, B>>>(ei);
    dinv_kernel<<<gN, B>>>();
    norm_kernel<<<gE, B>>>();

    transform_kernel<true><<<gN, B>>>(x, W1, nullptr);
    scatter_kernel<<<gE4, B>>>();
    transform_kernel<false><<<gN, B>>>(nullptr, W2, b1);
    scatter_kernel<<<gE4, B>>>();
    transform_kernel<false><<<gN, B>>>(nullptr, W3, b2);
    scatter_kernel<<<gE4, B>>>();

    pool_head_kernel<<<GG, B>>>(batch, b3, Wlin, blin, out);
}